// round 1
// baseline (speedup 1.0000x reference)
#include <cuda_runtime.h>
#include <math.h>

#define BB 4
#define NN 2048
#define DD 512
#define HH 8
#define EE 512
#define DD1 1024
#define HDD 128
#define MROWS (BB*NN)

// ---------------- scratch (device globals; no allocation allowed) ----------------
__device__ float g_xn[MROWS*DD];    // srms(x)
__device__ float g_u[MROWS*DD1];    // silu(xn@Wu+bu)            [b][n][c]
__device__ float g_v[MROWS*DD1];    // silu(xn@Wv+bv) transposed [b][h][n][hd]
__device__ float g_y[MROWS*DD1];    // u * conv                  [b][n][c]
__device__ float g_h1[NN*EE];
__device__ float g_t1[NN*EE];
__device__ float g_a[HH*NN*HDD];    // decay-scaled coef         [h][k][hd]

// ---------------- packed f32x2 FMA (sm_100+ FFMA2) ----------------
__device__ __forceinline__ void fma2(float2& d, float2 a, float2 b) {
    unsigned long long ud = *reinterpret_cast<unsigned long long*>(&d);
    unsigned long long ua = *reinterpret_cast<unsigned long long*>(&a);
    unsigned long long ub = *reinterpret_cast<unsigned long long*>(&b);
    asm("fma.rn.f32x2 %0, %1, %2, %0;" : "+l"(ud) : "l"(ua), "l"(ub));
    d = *reinterpret_cast<float2*>(&ud);
}

// ---------------- srms (cols fixed at 512), optional relu ----------------
__global__ void rms_kernel(const float* __restrict__ in, float* __restrict__ out, int relu_flag) {
    int row = blockIdx.x;
    float4 val = reinterpret_cast<const float4*>(in)[(size_t)row*128 + threadIdx.x];
    float ss = val.x*val.x + val.y*val.y + val.z*val.z + val.w*val.w;
    #pragma unroll
    for (int o = 16; o > 0; o >>= 1) ss += __shfl_xor_sync(0xffffffffu, ss, o);
    __shared__ float ws[4];
    if ((threadIdx.x & 31) == 0) ws[threadIdx.x >> 5] = ss;
    __syncthreads();
    float tot = ws[0] + ws[1] + ws[2] + ws[3];
    float inv = 1.0f / (sqrtf(tot * (1.0f/512.0f)) + 1e-8f);
    val.x *= inv; val.y *= inv; val.z *= inv; val.w *= inv;
    if (relu_flag) {
        val.x = fmaxf(val.x, 0.f); val.y = fmaxf(val.y, 0.f);
        val.z = fmaxf(val.z, 0.f); val.w = fmaxf(val.w, 0.f);
    }
    reinterpret_cast<float4*>(out)[(size_t)row*128 + threadIdx.x] = val;
}

// ---------------- hcf init: out[n][e] = n*Wp[e] + bp[e] ----------------
__global__ void posinit_kernel(const float* __restrict__ Wp, const float* __restrict__ bp,
                               float* __restrict__ out) {
    int n = blockIdx.x;
    int e = threadIdx.x * 4;
    float4 w = *reinterpret_cast<const float4*>(Wp + e);
    float4 b = *reinterpret_cast<const float4*>(bp + e);
    float fn = (float)n;
    float4 r;
    r.x = fn*w.x + b.x; r.y = fn*w.y + b.y; r.z = fn*w.z + b.z; r.w = fn*w.w + b.w;
    *reinterpret_cast<float4*>(out + (size_t)n*EE + e) = r;
}

// ---------------- generic tiled GEMM, f32x2 inner product ----------------
// C = A(MxK) @ W(KxN) + bias ; act: 0 none, 1 silu
// smode: 0 normal C ; 1 v-transpose into g_v ; 2 coef->g_a with gamma decay ;
//        3 add residual, store C
#define GBM 128
#define GBN 128
#define GBK 16

__global__ void __launch_bounds__(256) gemm_kernel(
    const float* __restrict__ A, const float* __restrict__ W,
    const float* __restrict__ bias, float* __restrict__ C,
    int M, int Nc, int K, int act, int smode, const float* __restrict__ resid)
{
    __shared__ float As[GBM][GBK];
    __shared__ float Bs[GBK][GBN];
    int bm = blockIdx.y * GBM;
    int bn = blockIdx.x * GBN;
    int tid = threadIdx.x;
    int tx = tid & 15;
    int ty = tid >> 4;
    float2 acc[8][4];
    #pragma unroll
    for (int i = 0; i < 8; i++)
        #pragma unroll
        for (int j = 0; j < 4; j++) acc[i][j] = make_float2(0.f, 0.f);

    int am  = tid >> 2;         // 0..63
    int ak  = (tid & 3) << 2;   // 0,4,8,12
    int bk  = tid >> 5;         // 0..7
    int bn4 = (tid & 31) << 2;  // 0..124

    for (int k0 = 0; k0 < K; k0 += GBK) {
        #pragma unroll
        for (int r = 0; r < 2; r++) {
            float4 v = *reinterpret_cast<const float4*>(A + (size_t)(bm + am + r*64)*K + k0 + ak);
            *reinterpret_cast<float4*>(&As[am + r*64][ak]) = v;
        }
        #pragma unroll
        for (int r = 0; r < 2; r++) {
            float4 v = *reinterpret_cast<const float4*>(W + (size_t)(k0 + bk + r*8)*Nc + bn + bn4);
            *reinterpret_cast<float4*>(&Bs[bk + r*8][bn4]) = v;
        }
        __syncthreads();
        #pragma unroll
        for (int k = 0; k < GBK; k++) {
            float af[8]; float2 bf[4];
            #pragma unroll
            for (int i = 0; i < 8; i++) af[i] = As[ty*8 + i][k];
            #pragma unroll
            for (int j = 0; j < 4; j++)
                bf[j] = reinterpret_cast<const float2*>(&Bs[k][0])[tx*4 + j];
            #pragma unroll
            for (int i = 0; i < 8; i++) {
                float2 a2 = make_float2(af[i], af[i]);
                #pragma unroll
                for (int j = 0; j < 4; j++) fma2(acc[i][j], a2, bf[j]);
            }
        }
        __syncthreads();
    }

    #pragma unroll
    for (int i = 0; i < 8; i++) {
        int r = bm + ty*8 + i;
        #pragma unroll
        for (int j = 0; j < 4; j++) {
            int c = bn + tx*8 + 2*j;
            float2 val = acc[i][j];
            val.x += bias[c]; val.y += bias[c+1];
            if (act == 1) {
                val.x = val.x / (1.0f + expf(-val.x));
                val.y = val.y / (1.0f + expf(-val.y));
            }
            if (smode == 0) {
                *reinterpret_cast<float2*>(C + (size_t)r*Nc + c) = val;
            } else if (smode == 1) {
                int b_ = r >> 11, nt = r & (NN-1);
                int h_ = c >> 7, hd = c & (HDD-1);
                *reinterpret_cast<float2*>(&g_v[(((size_t)(b_*HH + h_))*NN + nt)*HDD + hd]) = val;
            } else if (smode == 2) {
                // a[k] = coef[k] * gamma^k for k>=1, coef[0] for k==0
                float sc = (r == 0) ? 1.0f : expf((float)r * (-1.0005003335835335e-3f));
                int h_ = c >> 7, hd = c & (HDD-1);
                val.x *= sc; val.y *= sc;
                *reinterpret_cast<float2*>(&g_a[((size_t)h_*NN + r)*HDD + hd]) = val;
            } else {
                size_t o = (size_t)r*Nc + c;
                float2 rr = *reinterpret_cast<const float2*>(resid + o);
                val.x += rr.x; val.y += rr.y;
                *reinterpret_cast<float2*>(C + o) = val;
            }
        }
    }
}

// ---------------- causal conv: out[t,hd] = sum_{s<=t} a[t-s,hd]*v[s,hd] ----------------
// per block: one (b,h), 64 output times, all 128 hd. thread = 2 hd (f32x2) x 16 t.
// sliding a-window in registers -> per lag step: 1 LDS.64 + 8 FFMA2.
#define CSC 32
#define CTT 64
#define CKA 95   // CTT + CSC - 1 rows loaded (alloc 96)
#define CONV_SMEM ((CSC*HDD + 96*HDD)*4)

__global__ void __launch_bounds__(256) conv_kernel(
    const float* __restrict__ vg, const float* __restrict__ ag,
    const float* __restrict__ ug, float* __restrict__ yg)
{
    extern __shared__ float sm[];
    float2* v_sh = reinterpret_cast<float2*>(sm);             // [CSC][64]
    float2* a_sh = reinterpret_cast<float2*>(sm + CSC*HDD);   // [96][64]
    int bh = blockIdx.y;
    int b = bh >> 3, h = bh & 7;
    int t0 = (gridDim.x - 1 - blockIdx.x) * CTT;  // heavy tiles launch first
    int tid = threadIdx.x;
    int hdp = tid & 63;   // hd pair index (hd = 2*hdp)
    int tg  = tid >> 6;   // 0..3, 16 t each
    const float* vbase = vg + (size_t)bh * NN * HDD;
    const float* abase = ag + (size_t)h  * NN * HDD;
    float2 acc[16];
    #pragma unroll
    for (int i = 0; i < 16; i++) acc[i] = make_float2(0.f, 0.f);

    int s_end = t0 + CTT;
    for (int s0 = 0; s0 < s_end; s0 += CSC) {
        __syncthreads();
        #pragma unroll
        for (int i = 0; i < 4; i++) {
            int idx = tid + i*256;
            reinterpret_cast<float4*>(v_sh)[idx] =
                reinterpret_cast<const float4*>(vbase + (size_t)s0*HDD)[idx];
        }
        int kmin = t0 - s0 - (CSC - 1);
        for (int idx = tid; idx < CKA*(HDD/4); idx += 256) {
            int j  = idx >> 5;          // row (HDD/4 = 32 float4 per row)
            int c4 = (idx & 31) << 2;
            int k  = kmin + j;
            float4 av = (k >= 0) ? *reinterpret_cast<const float4*>(abase + (size_t)k*HDD + c4)
                                 : make_float4(0.f, 0.f, 0.f, 0.f);
            reinterpret_cast<float4*>(a_sh)[idx] = av;
        }
        __syncthreads();
        #pragma unroll 1
        for (int sb = 0; sb < CSC; sb += 8) {
            float2 vr[8];
            #pragma unroll
            for (int q = 0; q < 8; q++) vr[q] = v_sh[(sb + q)*64 + hdp];
            int wbase = tg*16 + (CSC - 1) - sb - 7;
            float2 w[8];
            #pragma unroll
            for (int q = 0; q < 8; q++) w[q] = a_sh[(wbase + q)*64 + hdp];
            #pragma unroll
            for (int tl = 0; tl < 16; tl++) {
                // acc[tl] += sum_q a_sh[wbase+tl+q] * v[sb + 7-q]
                #pragma unroll
                for (int q = 0; q < 8; q++) fma2(acc[tl], w[q], vr[7 - q]);
                #pragma unroll
                for (int q = 0; q < 7; q++) w[q] = w[q + 1];
                w[7] = a_sh[(wbase + tl + 8)*64 + hdp];  // row <= 95, alloc 96 (last value dead)
            }
        }
    }
    #pragma unroll
    for (int tl = 0; tl < 16; tl++) {
        int t = t0 + tg*16 + tl;
        size_t o = ((size_t)(b*NN + t))*DD1 + h*HDD + hdp*2;
        float2 uu = *reinterpret_cast<const float2*>(ug + o);
        float2 r = acc[tl];
        r.x *= uu.x; r.y *= uu.y;
        *reinterpret_cast<float2*>(yg + o) = r;
    }
}

// ---------------- launch ----------------
extern "C" void kernel_launch(void* const* d_in, const int* in_sizes, int n_in,
                              void* d_out, int out_size)
{
    const float* x  = (const float*)d_in[0];
    const float* Wu = (const float*)d_in[1];
    const float* bu = (const float*)d_in[2];
    const float* Wv = (const float*)d_in[3];
    const float* bv = (const float*)d_in[4];
    const float* Wo = (const float*)d_in[5];
    const float* bo = (const float*)d_in[6];
    const float* Wp = (const float*)d_in[7];
    const float* bp = (const float*)d_in[8];
    const float* W1 = (const float*)d_in[9];
    const float* b1 = (const float*)d_in[10];
    const float* W2 = (const float*)d_in[11];
    const float* b2 = (const float*)d_in[12];
    const float* W3 = (const float*)d_in[13];
    const float* b3 = (const float*)d_in[14];
    const float* Wz = (const float*)d_in[15];
    const float* bz = (const float*)d_in[16];
    float* out = (float*)d_out;

    float *xn, *u, *v, *y, *h1, *t1, *a;
    cudaGetSymbolAddress((void**)&xn, g_xn);
    cudaGetSymbolAddress((void**)&u,  g_u);
    cudaGetSymbolAddress((void**)&v,  g_v);
    cudaGetSymbolAddress((void**)&y,  g_y);
    cudaGetSymbolAddress((void**)&h1, g_h1);
    cudaGetSymbolAddress((void**)&t1, g_t1);
    cudaGetSymbolAddress((void**)&a,  g_a);

    cudaFuncSetAttribute(conv_kernel, cudaFuncAttributeMaxDynamicSharedMemorySize, CONV_SMEM);

    // xn = srms(x)
    rms_kernel<<<MROWS, 128>>>(x, xn, 0);
    // u = silu(xn@Wu + bu)
    gemm_kernel<<<dim3(DD1/GBN, MROWS/GBM), 256>>>(xn, Wu, bu, u, MROWS, DD1, DD, 1, 0, nullptr);
    // v (transposed [b][h][n][hd]) = silu(xn@Wv + bv)
    gemm_kernel<<<dim3(DD1/GBN, MROWS/GBM), 256>>>(xn, Wv, bv, nullptr, MROWS, DD1, DD, 1, 1, nullptr);
    // position MLP
    posinit_kernel<<<NN, 128>>>(Wp, bp, h1);
    rms_kernel<<<NN, 128>>>(h1, t1, 1);
    gemm_kernel<<<dim3(EE/GBN, NN/GBM), 256>>>(t1, W1, b1, h1, NN, EE, EE, 0, 0, nullptr);
    rms_kernel<<<NN, 128>>>(h1, t1, 1);
    gemm_kernel<<<dim3(EE/GBN, NN/GBM), 256>>>(t1, W2, b2, h1, NN, EE, EE, 0, 0, nullptr);
    rms_kernel<<<NN, 128>>>(h1, t1, 1);
    gemm_kernel<<<dim3(EE/GBN, NN/GBM), 256>>>(t1, W3, b3, h1, NN, EE, EE, 0, 0, nullptr);
    rms_kernel<<<NN, 128>>>(h1, t1, 1);
    // coef -> g_a (with gamma^k decay)
    gemm_kernel<<<dim3(DD1/GBN, NN/GBM), 256>>>(t1, Wz, bz, nullptr, NN, DD1, EE, 0, 2, nullptr);
    // y = u * causal_conv(a, v)
    conv_kernel<<<dim3(NN/CTT, BB*HH), 256, CONV_SMEM>>>(v, a, u, y);
    // out = y @ Wo + bo + x
    gemm_kernel<<<dim3(DD/GBN, MROWS/GBM), 256>>>(y, Wo, bo, out, MROWS, DD, DD1, 0, 3, x);
}

// round 3
// speedup vs baseline: 1.8809x; 1.8809x over previous
#include <cuda_runtime.h>
#include <math.h>
#include <stdint.h>

#define BB 4
#define NN 2048
#define DD 512
#define HH 8
#define EE 512
#define DD1 1024
#define HDD 128
#define MROWS (BB*NN)

// ---------------- scratch (device globals; no allocation allowed) ----------------
__device__ float g_xn[MROWS*DD];
__device__ float g_u[MROWS*DD1];
__device__ float g_v[MROWS*DD1];     // [b][h][n][hd]
__device__ float g_y[MROWS*DD1];
__device__ float g_h1[NN*EE];
__device__ float g_t1[NN*EE];
__device__ float g_a[HH*NN*HDD];     // [h][k][hd]
// transposed weights [N][K] fp32 (pre-rounded to tf32)
__device__ float g_WuT[DD1*DD];
__device__ float g_WvT[DD1*DD];
__device__ float g_WoT[DD*DD1];
__device__ float g_W1T[EE*EE];
__device__ float g_W2T[EE*EE];
__device__ float g_W3T[EE*EE];
__device__ float g_WzT[DD1*EE];

// ---------------- helpers ----------------
__device__ __forceinline__ uint32_t smem_u32(const void* p) {
    uint32_t a;
    asm("{ .reg .u64 t; cvta.to.shared.u64 t, %1; cvt.u32.u64 %0, t; }" : "=r"(a) : "l"(p));
    return a;
}
__device__ __forceinline__ float rtf(float f) {
    uint32_t r; asm("cvt.rna.tf32.f32 %0, %1;" : "=r"(r) : "f"(f));
    return __uint_as_float(r);
}
__device__ __forceinline__ void fma2(float2& d, float2 a, float2 b) {
    unsigned long long ud = *reinterpret_cast<unsigned long long*>(&d);
    unsigned long long ua = *reinterpret_cast<unsigned long long*>(&a);
    unsigned long long ub = *reinterpret_cast<unsigned long long*>(&b);
    asm("fma.rn.f32x2 %0, %1, %2, %0;" : "+l"(ud) : "l"(ua), "l"(ub));
    d = *reinterpret_cast<float2*>(&ud);
}
__device__ __forceinline__ void mma_tf32(float* c, const uint32_t* a, const uint32_t* b) {
    asm volatile(
        "mma.sync.aligned.m16n8k8.row.col.f32.tf32.tf32.f32 "
        "{%0,%1,%2,%3}, {%4,%5,%6,%7}, {%8,%9}, {%0,%1,%2,%3};"
        : "+f"(c[0]), "+f"(c[1]), "+f"(c[2]), "+f"(c[3])
        : "r"(a[0]), "r"(a[1]), "r"(a[2]), "r"(a[3]), "r"(b[0]), "r"(b[1]));
}

// ---------------- srms (cols fixed 512), optional relu; output rounded to tf32 ----------------
__global__ void rms_kernel(const float* __restrict__ in, float* __restrict__ out, int relu_flag) {
    int row = blockIdx.x;
    float4 val = reinterpret_cast<const float4*>(in)[(size_t)row*128 + threadIdx.x];
    float ss = val.x*val.x + val.y*val.y + val.z*val.z + val.w*val.w;
    #pragma unroll
    for (int o = 16; o > 0; o >>= 1) ss += __shfl_xor_sync(0xffffffffu, ss, o);
    __shared__ float ws[4];
    if ((threadIdx.x & 31) == 0) ws[threadIdx.x >> 5] = ss;
    __syncthreads();
    float tot = ws[0] + ws[1] + ws[2] + ws[3];
    float inv = 1.0f / (sqrtf(tot * (1.0f/512.0f)) + 1e-8f);
    val.x *= inv; val.y *= inv; val.z *= inv; val.w *= inv;
    if (relu_flag) {
        val.x = fmaxf(val.x, 0.f); val.y = fmaxf(val.y, 0.f);
        val.z = fmaxf(val.z, 0.f); val.w = fmaxf(val.w, 0.f);
    }
    val.x = rtf(val.x); val.y = rtf(val.y); val.z = rtf(val.z); val.w = rtf(val.w);
    reinterpret_cast<float4*>(out)[(size_t)row*128 + threadIdx.x] = val;
}

// ---------------- hcf init ----------------
__global__ void posinit_kernel(const float* __restrict__ Wp, const float* __restrict__ bp,
                               float* __restrict__ out) {
    int n = blockIdx.x;
    int e = threadIdx.x * 4;
    float4 w = *reinterpret_cast<const float4*>(Wp + e);
    float4 b = *reinterpret_cast<const float4*>(bp + e);
    float fn = (float)n;
    float4 r;
    r.x = fn*w.x + b.x; r.y = fn*w.y + b.y; r.z = fn*w.z + b.z; r.w = fn*w.w + b.w;
    *reinterpret_cast<float4*>(out + (size_t)n*EE + e) = r;
}

// ---------------- weight transpose: out[n][k] = tf32(in[k][n]) ----------------
__global__ void transpose_kernel(const float* __restrict__ in, float* __restrict__ out, int K, int N) {
    __shared__ float t[32][33];
    int n0 = blockIdx.x * 32, k0 = blockIdx.y * 32;
    int tx = threadIdx.x, ty = threadIdx.y;   // 32 x 8
    #pragma unroll
    for (int i = 0; i < 32; i += 8)
        t[ty + i][tx] = rtf(in[(size_t)(k0 + ty + i) * N + n0 + tx]);
    __syncthreads();
    #pragma unroll
    for (int i = 0; i < 32; i += 8)
        out[(size_t)(n0 + ty + i) * K + k0 + tx] = t[tx][ty + i];
}

// ---------------- mma.sync tf32 GEMM ----------------
// C(MxN) = A(MxK) @ Bt(NxK)^T + bias; tile 128x128, BK=32, 256 thr, warp tile 64x32
// act: 0 none, 1 silu. smode: 0 plain; 1 v-transpose; 2 coef->g_a decay; 3 +resid
#define TGBK 32
#define TILEF (128*TGBK)          // floats per tile buffer
#define TG_SMEM (4*TILEF*4)       // 65536 bytes

__global__ void __launch_bounds__(256) tgemm_kernel(
    const float* __restrict__ A, const float* __restrict__ Bt,
    const float* __restrict__ bias, float* __restrict__ C,
    int M, int Nc, int K, int act, int smode, const float* __restrict__ resid)
{
    extern __shared__ float smf[];
    float* AsBase = smf;              // [2][TILEF] swizzled
    float* BsBase = smf + 2*TILEF;
    int tid = threadIdx.x;
    int wid = tid >> 5, lane = tid & 31;
    int gid = lane >> 2, tc = lane & 3;
    int m0 = (wid >> 2) * 64, n0 = (wid & 3) * 32;
    int bm = blockIdx.y * 128, bn = blockIdx.x * 128;

    float acc[4][4][4];
    #pragma unroll
    for (int mi = 0; mi < 4; mi++)
        #pragma unroll
        for (int ni = 0; ni < 4; ni++)
            #pragma unroll
            for (int q = 0; q < 4; q++) acc[mi][ni][q] = 0.f;

    const float* Abase = A  + (size_t)bm * K;
    const float* Bbase = Bt + (size_t)bn * K;

    // chunk loader: 1024 float4 per tile, 4 per thread per operand
    int lrow = tid >> 1;                 // j = tid*? ... use j = tid + t*256
    (void)lrow;
    #define LD_CHUNK(buf, k0v) do { \
        float* dA = AsBase + (buf)*TILEF; \
        float* dB = BsBase + (buf)*TILEF; \
        _Pragma("unroll") \
        for (int t_ = 0; t_ < 4; t_++) { \
            int j = tid + t_*256; \
            int row = j >> 3, c4 = j & 7; \
            int soff = row*32 + ((c4 ^ (row & 7)) << 2); \
            uint32_t da = smem_u32(dA + soff); \
            const float* sa = Abase + (size_t)row*K + (k0v) + (c4 << 2); \
            asm volatile("cp.async.cg.shared.global [%0], [%1], 16;" :: "r"(da), "l"(sa)); \
            uint32_t db = smem_u32(dB + soff); \
            const float* sb = Bbase + (size_t)row*K + (k0v) + (c4 << 2); \
            asm volatile("cp.async.cg.shared.global [%0], [%1], 16;" :: "r"(db), "l"(sb)); \
        } \
        asm volatile("cp.async.commit_group;"); \
    } while (0)

    int nch = K >> 5;
    LD_CHUNK(0, 0);
    for (int ch = 0; ch < nch; ch++) {
        if (ch + 1 < nch) {
            LD_CHUNK((ch + 1) & 1, (ch + 1) << 5);
            asm volatile("cp.async.wait_group 1;");
        } else {
            asm volatile("cp.async.wait_group 0;");
        }
        __syncthreads();
        const uint32_t* Au = (const uint32_t*)(AsBase + (ch & 1)*TILEF);
        const uint32_t* Bu = (const uint32_t*)(BsBase + (ch & 1)*TILEF);
        #pragma unroll
        for (int ks = 0; ks < 4; ks++) {
            int f0 = ks*2, f1 = f0 + 1;
            int x0 = (((f0 ^ gid) << 2) + tc);
            int x1 = (((f1 ^ gid) << 2) + tc);
            uint32_t af[4][4], bf[4][2];
            #pragma unroll
            for (int mi = 0; mi < 4; mi++) {
                int ra = (m0 + mi*16 + gid) * 32;
                int rb = ra + 8*32;
                af[mi][0] = Au[ra + x0]; af[mi][1] = Au[rb + x0];
                af[mi][2] = Au[ra + x1]; af[mi][3] = Au[rb + x1];
            }
            #pragma unroll
            for (int ni = 0; ni < 4; ni++) {
                int rn = (n0 + ni*8 + gid) * 32;
                bf[ni][0] = Bu[rn + x0];
                bf[ni][1] = Bu[rn + x1];
            }
            #pragma unroll
            for (int mi = 0; mi < 4; mi++)
                #pragma unroll
                for (int ni = 0; ni < 4; ni++)
                    mma_tf32(acc[mi][ni], af[mi], bf[ni]);
        }
        __syncthreads();
    }

    // epilogue: lane holds C[r][c],C[r][c+1] (q0,q1) and C[r+8][c],C[r+8][c+1] (q2,q3)
    #pragma unroll
    for (int mi = 0; mi < 4; mi++) {
        #pragma unroll
        for (int ni = 0; ni < 4; ni++) {
            #pragma unroll
            for (int half = 0; half < 2; half++) {
                int r = bm + m0 + mi*16 + gid + half*8;
                int c = bn + n0 + ni*8 + 2*tc;
                float2 val = make_float2(acc[mi][ni][half*2], acc[mi][ni][half*2 + 1]);
                float2 bi = *reinterpret_cast<const float2*>(bias + c);
                val.x += bi.x; val.y += bi.y;
                if (act == 1) {
                    val.x = val.x / (1.0f + expf(-val.x));
                    val.y = val.y / (1.0f + expf(-val.y));
                }
                if (smode == 0) {
                    *reinterpret_cast<float2*>(C + (size_t)r * Nc + c) = val;
                } else if (smode == 1) {
                    int b_ = r >> 11, nt = r & (NN - 1);
                    int h_ = c >> 7, hd = c & (HDD - 1);
                    *reinterpret_cast<float2*>(&g_v[(((size_t)(b_*HH + h_))*NN + nt)*HDD + hd]) = val;
                } else if (smode == 2) {
                    float sc = (r == 0) ? 1.0f : expf((float)r * (-1.0005003335835335e-3f));
                    int h_ = c >> 7, hd = c & (HDD - 1);
                    val.x *= sc; val.y *= sc;
                    *reinterpret_cast<float2*>(&g_a[((size_t)h_*NN + r)*HDD + hd]) = val;
                } else {
                    size_t o = (size_t)r * Nc + c;
                    float2 rr = *reinterpret_cast<const float2*>(resid + o);
                    val.x += rr.x; val.y += rr.y;
                    *reinterpret_cast<float2*>(C + o) = val;
                }
            }
        }
    }
}

// ---------------- causal conv (SIMT f32x2); y output rounded to tf32 ----------------
#define CSC 32
#define CTT 64
#define CKA 95
#define CONV_SMEM ((CSC*HDD + 96*HDD)*4)

__global__ void __launch_bounds__(256) conv_kernel(
    const float* __restrict__ vg, const float* __restrict__ ag,
    const float* __restrict__ ug, float* __restrict__ yg)
{
    extern __shared__ float sm[];
    float2* v_sh = reinterpret_cast<float2*>(sm);
    float2* a_sh = reinterpret_cast<float2*>(sm + CSC*HDD);
    int bh = blockIdx.y;
    int b = bh >> 3, h = bh & 7;
    int t0 = (gridDim.x - 1 - blockIdx.x) * CTT;
    int tid = threadIdx.x;
    int hdp = tid & 63;
    int tg  = tid >> 6;
    const float* vbase = vg + (size_t)bh * NN * HDD;
    const float* abase = ag + (size_t)h  * NN * HDD;
    float2 acc[16];
    #pragma unroll
    for (int i = 0; i < 16; i++) acc[i] = make_float2(0.f, 0.f);

    int s_end = t0 + CTT;
    for (int s0 = 0; s0 < s_end; s0 += CSC) {
        __syncthreads();
        #pragma unroll
        for (int i = 0; i < 4; i++) {
            int idx = tid + i*256;
            reinterpret_cast<float4*>(v_sh)[idx] =
                reinterpret_cast<const float4*>(vbase + (size_t)s0*HDD)[idx];
        }
        int kmin = t0 - s0 - (CSC - 1);
        for (int idx = tid; idx < CKA*(HDD/4); idx += 256) {
            int j  = idx >> 5;
            int c4 = (idx & 31) << 2;
            int k  = kmin + j;
            float4 av = (k >= 0) ? *reinterpret_cast<const float4*>(abase + (size_t)k*HDD + c4)
                                 : make_float4(0.f, 0.f, 0.f, 0.f);
            reinterpret_cast<float4*>(a_sh)[idx] = av;
        }
        __syncthreads();
        #pragma unroll 1
        for (int sb = 0; sb < CSC; sb += 8) {
            float2 vr[8];
            #pragma unroll
            for (int q = 0; q < 8; q++) vr[q] = v_sh[(sb + q)*64 + hdp];
            int wbase = tg*16 + (CSC - 1) - sb - 7;
            float2 w[8];
            #pragma unroll
            for (int q = 0; q < 8; q++) w[q] = a_sh[(wbase + q)*64 + hdp];
            #pragma unroll
            for (int tl = 0; tl < 16; tl++) {
                #pragma unroll
                for (int q = 0; q < 8; q++) fma2(acc[tl], w[q], vr[7 - q]);
                #pragma unroll
                for (int q = 0; q < 7; q++) w[q] = w[q + 1];
                w[7] = a_sh[(wbase + tl + 8)*64 + hdp];
            }
        }
    }
    #pragma unroll
    for (int tl = 0; tl < 16; tl++) {
        int t = t0 + tg*16 + tl;
        size_t o = ((size_t)(b*NN + t))*DD1 + h*HDD + hdp*2;
        float2 uu = *reinterpret_cast<const float2*>(ug + o);
        float2 r = acc[tl];
        r.x = rtf(r.x * uu.x); r.y = rtf(r.y * uu.y);
        *reinterpret_cast<float2*>(yg + o) = r;
    }
}

// ---------------- launch ----------------
extern "C" void kernel_launch(void* const* d_in, const int* in_sizes, int n_in,
                              void* d_out, int out_size)
{
    const float* x  = (const float*)d_in[0];
    const float* Wu = (const float*)d_in[1];
    const float* bu = (const float*)d_in[2];
    const float* Wv = (const float*)d_in[3];
    const float* bv = (const float*)d_in[4];
    const float* Wo = (const float*)d_in[5];
    const float* bo = (const float*)d_in[6];
    const float* Wp = (const float*)d_in[7];
    const float* bp = (const float*)d_in[8];
    const float* W1 = (const float*)d_in[9];
    const float* b1 = (const float*)d_in[10];
    const float* W2 = (const float*)d_in[11];
    const float* b2 = (const float*)d_in[12];
    const float* W3 = (const float*)d_in[13];
    const float* b3 = (const float*)d_in[14];
    const float* Wz = (const float*)d_in[15];
    const float* bz = (const float*)d_in[16];
    float* out = (float*)d_out;

    float *xn, *u, *v, *y, *h1, *t1, *a;
    float *wut, *wvt, *wot, *w1t, *w2t, *w3t, *wzt;
    cudaGetSymbolAddress((void**)&xn, g_xn);
    cudaGetSymbolAddress((void**)&u,  g_u);
    cudaGetSymbolAddress((void**)&v,  g_v);
    cudaGetSymbolAddress((void**)&y,  g_y);
    cudaGetSymbolAddress((void**)&h1, g_h1);
    cudaGetSymbolAddress((void**)&t1, g_t1);
    cudaGetSymbolAddress((void**)&a,  g_a);
    cudaGetSymbolAddress((void**)&wut, g_WuT);
    cudaGetSymbolAddress((void**)&wvt, g_WvT);
    cudaGetSymbolAddress((void**)&wot, g_WoT);
    cudaGetSymbolAddress((void**)&w1t, g_W1T);
    cudaGetSymbolAddress((void**)&w2t, g_W2T);
    cudaGetSymbolAddress((void**)&w3t, g_W3T);
    cudaGetSymbolAddress((void**)&wzt, g_WzT);

    cudaFuncSetAttribute(conv_kernel, cudaFuncAttributeMaxDynamicSharedMemorySize, CONV_SMEM);
    cudaFuncSetAttribute(tgemm_kernel, cudaFuncAttributeMaxDynamicSharedMemorySize, TG_SMEM);

    dim3 tt(32, 8);
    transpose_kernel<<<dim3(DD1/32, DD/32),  tt>>>(Wu, wut, DD,  DD1);
    transpose_kernel<<<dim3(DD1/32, DD/32),  tt>>>(Wv, wvt, DD,  DD1);
    transpose_kernel<<<dim3(DD/32,  DD1/32), tt>>>(Wo, wot, DD1, DD);
    transpose_kernel<<<dim3(EE/32,  EE/32),  tt>>>(W1, w1t, EE,  EE);
    transpose_kernel<<<dim3(EE/32,  EE/32),  tt>>>(W2, w2t, EE,  EE);
    transpose_kernel<<<dim3(EE/32,  EE/32),  tt>>>(W3, w3t, EE,  EE);
    transpose_kernel<<<dim3(DD1/32, EE/32),  tt>>>(Wz, wzt, EE,  DD1);

    rms_kernel<<<MROWS, 128>>>(x, xn, 0);
    tgemm_kernel<<<dim3(DD1/128, MROWS/128), 256, TG_SMEM>>>(xn, wut, bu, u, MROWS, DD1, DD, 1, 0, nullptr);
    tgemm_kernel<<<dim3(DD1/128, MROWS/128), 256, TG_SMEM>>>(xn, wvt, bv, nullptr, MROWS, DD1, DD, 1, 1, nullptr);

    posinit_kernel<<<NN, 128>>>(Wp, bp, h1);
    rms_kernel<<<NN, 128>>>(h1, t1, 1);
    tgemm_kernel<<<dim3(EE/128, NN/128), 256, TG_SMEM>>>(t1, w1t, b1, h1, NN, EE, EE, 0, 0, nullptr);
    rms_kernel<<<NN, 128>>>(h1, t1, 1);
    tgemm_kernel<<<dim3(EE/128, NN/128), 256, TG_SMEM>>>(t1, w2t, b2, h1, NN, EE, EE, 0, 0, nullptr);
    rms_kernel<<<NN, 128>>>(h1, t1, 1);
    tgemm_kernel<<<dim3(EE/128, NN/128), 256, TG_SMEM>>>(t1, w3t, b3, h1, NN, EE, EE, 0, 0, nullptr);
    rms_kernel<<<NN, 128>>>(h1, t1, 1);
    tgemm_kernel<<<dim3(DD1/128, NN/128), 256, TG_SMEM>>>(t1, wzt, bz, nullptr, NN, DD1, EE, 0, 2, nullptr);

    conv_kernel<<<dim3(NN/CTT, BB*HH), 256, CONV_SMEM>>>(v, a, u, y);

    tgemm_kernel<<<dim3(DD/128, MROWS/128), 256, TG_SMEM>>>(y, wot, bo, out, MROWS, DD, DD1, 0, 3, x);
}